// round 8
// baseline (speedup 1.0000x reference)
#include <cuda_runtime.h>
#include <cstdint>

// Chamfer distance, B=4, N=4096, D=3, single fused kernel, 1024 blocks.
//
// min_j ||a-b_j||^2 = |a|^2 + min_j (|b_j|^2 - 2 a.b_j)
// Inner: per 2 b-points x 4 a-points: 2 LDS.128 + 4x(3 fma.rn.f32x2 + 2 FMNMX)
//        = 2.75 instr/pair.
//
// Grid: (4 a-chunks, 4 batches, 64 = dir*32 + slice), 256 threads.
// Slice = 128 b-points in shared as packed quads (LDS.128 register quads
// ARE the f32x2 operands). Each block writes per-slice partial mins to
// g_part[point][32] (no atomics, no init needed).
// Hierarchical tail: per-group (dir,batch,achunk = 32 groups of 32
// slice-blocks) last-finisher reduces its 1024 points (overlapped with
// other groups' compute), globally-last group sums 32 partials in fixed
// order. Counters self-reset (graph-replay safe); deterministic.

#define NB 4
#define NP 4096
#define NSLOT (2 * NB * NP) /* 32768 */
#define NSLICE 32
#define NGROUP 32

__device__ float g_part[NSLOT * NSLICE];  // [point][slice], 4MB
__device__ float g_gsum[NGROUP];
__device__ int g_cnt[NGROUP];  // zero-init; self-resetting
__device__ int g_done;         // zero-init; self-resetting

__device__ __forceinline__ unsigned long long pack2(float lo, float hi) {
    unsigned long long r;
    asm("mov.b64 %0, {%1, %2};" : "=l"(r) : "f"(lo), "f"(hi));
    return r;
}
__device__ __forceinline__ void unpack2(unsigned long long v, float& lo, float& hi) {
    asm("mov.b64 {%0, %1}, %2;" : "=f"(lo), "=f"(hi) : "l"(v));
}
__device__ __forceinline__ unsigned long long fmafx2(unsigned long long a, unsigned long long b,
                                                     unsigned long long c) {
    unsigned long long r;
    asm("fma.rn.f32x2 %0, %1, %2, %3;" : "=l"(r) : "l"(a), "l"(b), "l"(c));
    return r;
}

__global__ __launch_bounds__(256, 6) void chamfer_fused(const float* __restrict__ pc1,
                                                        const float* __restrict__ pc2,
                                                        float* __restrict__ out) {
    // 128 b-points as 64 packed pairs:
    // s1[j] = (bx0,bx1,by0,by1), s2[j] = (bz0,bz1,bw0,bw1), w = |b|^2
    __shared__ ulonglong2 s1[64];
    __shared__ ulonglong2 s2[64];
    __shared__ float red[256];
    __shared__ int flag;

    const int tid = threadIdx.x;
    const int achunk = blockIdx.x;      // 0..3  (1024 a-points)
    const int batch = blockIdx.y;       // 0..3
    const int dir = blockIdx.z >> 5;    // 0: pc1->pc2, 1: pc2->pc1
    const int slice = blockIdx.z & 31;  // 0..31 (128 b-points)
    const int group = dir * 16 + batch * 4 + achunk;

    const float* Abase = (dir ? pc2 : pc1) + (size_t)batch * NP * 3;
    const float* Bbase = (dir ? pc1 : pc2) + (size_t)batch * NP * 3 + (size_t)slice * 128 * 3;

    // Fill shared b-slice (threads 0..127, 1 point each).
    if (tid < 128) {
        float bx = Bbase[tid * 3 + 0];
        float by = Bbase[tid * 3 + 1];
        float bz = Bbase[tid * 3 + 2];
        float bw = bx * bx + by * by + bz * bz;
        int pair = tid >> 1, half = tid & 1;
        float* p1 = (float*)&s1[pair];
        float* p2 = (float*)&s2[pair];
        p1[half] = bx;
        p1[2 + half] = by;
        p2[half] = bz;
        p2[2 + half] = bw;
    }
    __syncthreads();

    // Each thread owns 4 a-points.
    unsigned long long nax[4], nay[4], naz[4];
    float asq[4], mlo[4], mhi[4];
#pragma unroll
    for (int k = 0; k < 4; ++k) {
        int p = achunk * 1024 + k * 256 + tid;
        float ax = Abase[p * 3 + 0];
        float ay = Abase[p * 3 + 1];
        float az = Abase[p * 3 + 2];
        nax[k] = pack2(-2.0f * ax, -2.0f * ax);
        nay[k] = pack2(-2.0f * ay, -2.0f * ay);
        naz[k] = pack2(-2.0f * az, -2.0f * az);
        asq[k] = ax * ax + ay * ay + az * az;
        mlo[k] = 3.4e38f;
        mhi[k] = 3.4e38f;
    }

#pragma unroll 4
    for (int j = 0; j < 64; ++j) {
        ulonglong2 v1 = s1[j];  // x=(bx0,bx1) y=(by0,by1)
        ulonglong2 v2 = s2[j];  // x=(bz0,bz1) y=(bw0,bw1)
#pragma unroll
        for (int k = 0; k < 4; ++k) {
            unsigned long long t = fmafx2(naz[k], v2.x, v2.y);  // bw - 2az*bz
            t = fmafx2(nay[k], v1.y, t);
            t = fmafx2(nax[k], v1.x, t);
            float lo, hi;
            unpack2(t, lo, hi);
            mlo[k] = fminf(mlo[k], lo);
            mhi[k] = fminf(mhi[k], hi);
        }
    }

    // Partial mins (|a|^2 folded in, clamped at 0) -> g_part[point][slice].
    const int pbase = dir * (NB * NP) + batch * NP + achunk * 1024;
#pragma unroll
    for (int k = 0; k < 4; ++k) {
        float m = fmaxf(asq[k] + fminf(mlo[k], mhi[k]), 0.0f);
        g_part[(size_t)(pbase + k * 256 + tid) * NSLICE + slice] = m;
    }

    // ---- Group finalize (last of 32 slice-blocks in this group) ----
    __threadfence();
    if (tid == 0) {
        int c = atomicAdd(&g_cnt[group], 1);
        flag = (c == NSLICE - 1);
        if (flag) g_cnt[group] = 0;  // self-reset for graph replay
    }
    __syncthreads();
    if (!flag) return;
    __threadfence();  // acquire: other slice-blocks' g_part writes

    float s = 0.0f;
#pragma unroll
    for (int k = 0; k < 4; ++k) {
        const float* row = &g_part[(size_t)(pbase + k * 256 + tid) * NSLICE];
        float m = 3.4e38f;
#pragma unroll
        for (int q = 0; q < NSLICE / 4; ++q) {
            float4 v = *(const float4*)(row + q * 4);
            m = fminf(m, fminf(fminf(v.x, v.y), fminf(v.z, v.w)));
        }
        s += sqrtf(m);
    }
    red[tid] = s;
    __syncthreads();
#pragma unroll
    for (int off = 128; off > 0; off >>= 1) {
        if (tid < off) red[tid] += red[tid + off];
        __syncthreads();
    }

    // ---- Global finalize (last of 32 groups) ----
    if (tid == 0) {
        g_gsum[group] = red[0];
        __threadfence();
        int c = atomicAdd(&g_done, 1);
        if (c == NGROUP - 1) {
            g_done = 0;  // self-reset
            __threadfence();
            float total = 0.0f;
            for (int g = 0; g < NGROUP; ++g) total += g_gsum[g];
            out[0] = total * (1.0f / (float)NSLOT);
        }
    }
}

extern "C" void kernel_launch(void* const* d_in, const int* in_sizes, int n_in,
                              void* d_out, int out_size) {
    const float* pc1 = (const float*)d_in[0];
    const float* pc2 = (const float*)d_in[1];
    chamfer_fused<<<dim3(4, 4, 64), 256>>>(pc1, pc2, (float*)d_out);
}

// round 12
// speedup vs baseline: 1.2216x; 1.2216x over previous
#include <cuda_runtime.h>
#include <cstdint>

// Chamfer distance, B=4, N=4096, D=3, single fused kernel, 512 blocks x 128thr.
//
// min_j ||a-b_j||^2 = |a|^2 + min_j (|b_j|^2 - 2 a.b_j)
// K=8 a-points per thread so each broadcast LDS.128 pair feeds 8x
// (3 fma.rn.f32x2 + 2 FMNMX): shared-crossbar cycles per FLOP halved vs K=4
// (the round-5 kernel was LSU-bound, not FMA-bound).
//
// Grid: (4 a-chunks, 4 batches, 32 = dir*16 + slice), 128 threads.
// Block covers 1024 a-points (128 thr x K=8) vs one 256-b-point slice held
// in shared as packed quads (LDS.128 register quads ARE the f32x2 operands).
// Per-slice partial mins -> g_part[point][16] (no atomics, no init).
// Hierarchical tail: per-group (dir,batch,achunk = 32 groups of 16
// slice-blocks) last-finisher reduces its 1024 points, globally-last group
// sums 32 partials in fixed order. Counters self-reset (graph-replay safe);
// fixed-order reductions -> deterministic.

#define NB 4
#define NP 4096
#define NSLOT (2 * NB * NP) /* 32768 */
#define NSLICE 16
#define NGROUP 32
#define KA 8
#define NT 128

__device__ float g_part[NSLOT * NSLICE];  // [point][slice], 2MB
__device__ float g_gsum[NGROUP];
__device__ int g_cnt[NGROUP];  // zero-init; self-resetting
__device__ int g_done;         // zero-init; self-resetting

__device__ __forceinline__ unsigned long long pack2(float lo, float hi) {
    unsigned long long r;
    asm("mov.b64 %0, {%1, %2};" : "=l"(r) : "f"(lo), "f"(hi));
    return r;
}
__device__ __forceinline__ void unpack2(unsigned long long v, float& lo, float& hi) {
    asm("mov.b64 {%0, %1}, %2;" : "=f"(lo), "=f"(hi) : "l"(v));
}
__device__ __forceinline__ unsigned long long fmafx2(unsigned long long a, unsigned long long b,
                                                     unsigned long long c) {
    unsigned long long r;
    asm("fma.rn.f32x2 %0, %1, %2, %3;" : "=l"(r) : "l"(a), "l"(b), "l"(c));
    return r;
}

__global__ __launch_bounds__(NT, 5) void chamfer_fused(const float* __restrict__ pc1,
                                                       const float* __restrict__ pc2,
                                                       float* __restrict__ out) {
    // 256 b-points as 128 packed pairs:
    // s1[j] = (bx0,bx1,by0,by1), s2[j] = (bz0,bz1,bw0,bw1), w = |b|^2
    __shared__ ulonglong2 s1[128];
    __shared__ ulonglong2 s2[128];
    __shared__ float red[NT];
    __shared__ int flag;

    const int tid = threadIdx.x;
    const int achunk = blockIdx.x;      // 0..3  (1024 a-points)
    const int batch = blockIdx.y;       // 0..3
    const int dir = blockIdx.z >> 4;    // 0: pc1->pc2, 1: pc2->pc1
    const int slice = blockIdx.z & 15;  // 0..15 (256 b-points)
    const int group = dir * 16 + batch * 4 + achunk;

    const float* Abase = (dir ? pc2 : pc1) + (size_t)batch * NP * 3;
    const float* Bbase = (dir ? pc1 : pc2) + (size_t)batch * NP * 3 + (size_t)slice * 256 * 3;

    // Fill shared b-slice (2 points per thread).
#pragma unroll
    for (int r = 0; r < 2; ++r) {
        int jp = r * NT + tid;
        float bx = Bbase[jp * 3 + 0];
        float by = Bbase[jp * 3 + 1];
        float bz = Bbase[jp * 3 + 2];
        float bw = bx * bx + by * by + bz * bz;
        int pair = jp >> 1, half = jp & 1;
        float* p1 = (float*)&s1[pair];
        float* p2 = (float*)&s2[pair];
        p1[half] = bx;
        p1[2 + half] = by;
        p2[half] = bz;
        p2[2 + half] = bw;
    }
    __syncthreads();

    // Each thread owns KA=8 a-points.
    unsigned long long nax[KA], nay[KA], naz[KA];
    float asq[KA], mlo[KA], mhi[KA];
#pragma unroll
    for (int k = 0; k < KA; ++k) {
        int p = achunk * 1024 + k * NT + tid;
        float ax = Abase[p * 3 + 0];
        float ay = Abase[p * 3 + 1];
        float az = Abase[p * 3 + 2];
        nax[k] = pack2(-2.0f * ax, -2.0f * ax);
        nay[k] = pack2(-2.0f * ay, -2.0f * ay);
        naz[k] = pack2(-2.0f * az, -2.0f * az);
        asq[k] = ax * ax + ay * ay + az * az;
        mlo[k] = 3.4e38f;
        mhi[k] = 3.4e38f;
    }

#pragma unroll 2
    for (int j = 0; j < 128; ++j) {
        ulonglong2 v1 = s1[j];  // x=(bx0,bx1) y=(by0,by1)
        ulonglong2 v2 = s2[j];  // x=(bz0,bz1) y=(bw0,bw1)
#pragma unroll
        for (int k = 0; k < KA; ++k) {
            unsigned long long t = fmafx2(naz[k], v2.x, v2.y);  // bw - 2az*bz
            t = fmafx2(nay[k], v1.y, t);
            t = fmafx2(nax[k], v1.x, t);
            float lo, hi;
            unpack2(t, lo, hi);
            mlo[k] = fminf(mlo[k], lo);
            mhi[k] = fminf(mhi[k], hi);
        }
    }

    // Partial mins (|a|^2 folded in, clamped at 0) -> g_part[point][slice].
    const int pbase = dir * (NB * NP) + batch * NP + achunk * 1024;
#pragma unroll
    for (int k = 0; k < KA; ++k) {
        float mm = fmaxf(asq[k] + fminf(mlo[k], mhi[k]), 0.0f);
        g_part[(size_t)(pbase + k * NT + tid) * NSLICE + slice] = mm;
    }

    // ---- Group finalize (last of 16 slice-blocks in this group) ----
    __threadfence();
    if (tid == 0) {
        int c = atomicAdd(&g_cnt[group], 1);
        flag = (c == NSLICE - 1);
        if (flag) g_cnt[group] = 0;  // self-reset for graph replay
    }
    __syncthreads();
    if (!flag) return;
    __threadfence();  // acquire: other slice-blocks' g_part writes

    float s = 0.0f;
#pragma unroll
    for (int k = 0; k < KA; ++k) {
        const float* row = &g_part[(size_t)(pbase + k * NT + tid) * NSLICE];
        float mm = 3.4e38f;
#pragma unroll
        for (int q = 0; q < NSLICE / 4; ++q) {
            float4 v = *(const float4*)(row + q * 4);
            mm = fminf(mm, fminf(fminf(v.x, v.y), fminf(v.z, v.w)));
        }
        s += sqrtf(mm);
    }
    red[tid] = s;
    __syncthreads();
#pragma unroll
    for (int off = NT / 2; off > 0; off >>= 1) {
        if (tid < off) red[tid] += red[tid + off];
        __syncthreads();
    }

    // ---- Global finalize (last of 32 groups) ----
    if (tid == 0) {
        g_gsum[group] = red[0];
        __threadfence();
        int c = atomicAdd(&g_done, 1);
        if (c == NGROUP - 1) {
            g_done = 0;  // self-reset
            __threadfence();
            float total = 0.0f;
            for (int g = 0; g < NGROUP; ++g) total += g_gsum[g];
            out[0] = total * (1.0f / (float)NSLOT);
        }
    }
}

extern "C" void kernel_launch(void* const* d_in, const int* in_sizes, int n_in,
                              void* d_out, int out_size) {
    const float* pc1 = (const float*)d_in[0];
    const float* pc2 = (const float*)d_in[1];
    chamfer_fused<<<dim3(4, 4, 32), NT>>>(pc1, pc2, (float*)d_out);
}

// round 13
// speedup vs baseline: 1.3105x; 1.0727x over previous
#include <cuda_runtime.h>
#include <cstdint>

// Chamfer distance, B=4, N=4096, D=3, single fused kernel, 1024 x 64thr.
//
// min_j ||a-b_j||^2 = |a|^2 + min_j (|b_j|^2 - 2 a.b_j)
// KA=8 a-points/thread; per b-pair j: 2 LDS.128 (broadcast, prefetched) +
// 8 x (3 fma.rn.f32x2 + 2 FMNMX) = 2.6 issue-slots/pair. FFMA2 measured
// full-rate (rt 2) on sm_103a.
//
// Grid: (8 a-chunks x 512, 4 batches, 32 = dir*16 + slice), 64 threads.
// 1024 blocks, <=10 blocks/SM by regs -> single wave, 6-7 blocks/SM
// (better SM load balance than 512-block config: max 7/32 vs 4/16 units).
// s1/s2 hold one 256-b-point slice as packed quads (LDS.128 register quads
// ARE the f32x2 operands); next-j prefetch hides the 29-cyc LDS latency.
// Per-slice partial mins -> g_part[point][16] (no atomics, no init).
// Hierarchical tail: per-group (dir,batch,achunk = 64 groups of 16
// slice-blocks) last-finisher reduces its 512 points, globally-last group
// sums 64 partials in fixed order. Counters self-reset (graph-replay
// safe); fixed-order reductions -> deterministic.

#define NB 4
#define NP 4096
#define NSLOT (2 * NB * NP) /* 32768 */
#define NSLICE 16
#define NGROUP 64
#define KA 8
#define NT 64
#define APB (NT * KA) /* 512 a-points per block */

__device__ float g_part[NSLOT * NSLICE];  // [point][slice], 2MB
__device__ float g_gsum[NGROUP];
__device__ int g_cnt[NGROUP];  // zero-init; self-resetting
__device__ int g_done;         // zero-init; self-resetting

__device__ __forceinline__ unsigned long long pack2(float lo, float hi) {
    unsigned long long r;
    asm("mov.b64 %0, {%1, %2};" : "=l"(r) : "f"(lo), "f"(hi));
    return r;
}
__device__ __forceinline__ void unpack2(unsigned long long v, float& lo, float& hi) {
    asm("mov.b64 {%0, %1}, %2;" : "=f"(lo), "=f"(hi) : "l"(v));
}
__device__ __forceinline__ unsigned long long fmafx2(unsigned long long a, unsigned long long b,
                                                     unsigned long long c) {
    unsigned long long r;
    asm("fma.rn.f32x2 %0, %1, %2, %3;" : "=l"(r) : "l"(a), "l"(b), "l"(c));
    return r;
}

__global__ __launch_bounds__(NT, 10) void chamfer_fused(const float* __restrict__ pc1,
                                                        const float* __restrict__ pc2,
                                                        float* __restrict__ out) {
    // 256 b-points as 128 packed pairs:
    // s1[j] = (bx0,bx1,by0,by1), s2[j] = (bz0,bz1,bw0,bw1), w = |b|^2
    __shared__ ulonglong2 s1[128];
    __shared__ ulonglong2 s2[128];
    __shared__ float red[NT];
    __shared__ int flag;

    const int tid = threadIdx.x;
    const int achunk = blockIdx.x;      // 0..7  (512 a-points)
    const int batch = blockIdx.y;       // 0..3
    const int dir = blockIdx.z >> 4;    // 0: pc1->pc2, 1: pc2->pc1
    const int slice = blockIdx.z & 15;  // 0..15 (256 b-points)
    const int group = dir * 32 + batch * 8 + achunk;

    const float* Abase = (dir ? pc2 : pc1) + (size_t)batch * NP * 3;
    const float* Bbase = (dir ? pc1 : pc2) + (size_t)batch * NP * 3 + (size_t)slice * 256 * 3;

    // Fill shared b-slice (4 points per thread).
#pragma unroll
    for (int r = 0; r < 4; ++r) {
        int jp = r * NT + tid;
        float bx = Bbase[jp * 3 + 0];
        float by = Bbase[jp * 3 + 1];
        float bz = Bbase[jp * 3 + 2];
        float bw = bx * bx + by * by + bz * bz;
        int pair = jp >> 1, half = jp & 1;
        float* p1 = (float*)&s1[pair];
        float* p2 = (float*)&s2[pair];
        p1[half] = bx;
        p1[2 + half] = by;
        p2[half] = bz;
        p2[2 + half] = bw;
    }
    __syncthreads();

    // Each thread owns KA=8 a-points.
    unsigned long long nax[KA], nay[KA], naz[KA];
    float asq[KA], mlo[KA], mhi[KA];
#pragma unroll
    for (int k = 0; k < KA; ++k) {
        int p = achunk * APB + k * NT + tid;
        float ax = Abase[p * 3 + 0];
        float ay = Abase[p * 3 + 1];
        float az = Abase[p * 3 + 2];
        nax[k] = pack2(-2.0f * ax, -2.0f * ax);
        nay[k] = pack2(-2.0f * ay, -2.0f * ay);
        naz[k] = pack2(-2.0f * az, -2.0f * az);
        asq[k] = ax * ax + ay * ay + az * az;
        mlo[k] = 3.4e38f;
        mhi[k] = 3.4e38f;
    }

    // Main loop with explicit next-j prefetch (hides LDS latency).
    ulonglong2 p1v = s1[0];
    ulonglong2 p2v = s2[0];
#pragma unroll 2
    for (int j = 0; j < 128; ++j) {
        ulonglong2 v1 = p1v;  // x=(bx0,bx1) y=(by0,by1)
        ulonglong2 v2 = p2v;  // x=(bz0,bz1) y=(bw0,bw1)
        int jn = (j + 1) & 127;
        p1v = s1[jn];
        p2v = s2[jn];
#pragma unroll
        for (int k = 0; k < KA; ++k) {
            unsigned long long t = fmafx2(naz[k], v2.x, v2.y);  // bw - 2az*bz
            t = fmafx2(nay[k], v1.y, t);
            t = fmafx2(nax[k], v1.x, t);
            float lo, hi;
            unpack2(t, lo, hi);
            mlo[k] = fminf(mlo[k], lo);
            mhi[k] = fminf(mhi[k], hi);
        }
    }

    // Partial mins (|a|^2 folded in, clamped at 0) -> g_part[point][slice].
    const int pbase = dir * (NB * NP) + batch * NP + achunk * APB;
#pragma unroll
    for (int k = 0; k < KA; ++k) {
        float mm = fmaxf(asq[k] + fminf(mlo[k], mhi[k]), 0.0f);
        g_part[(size_t)(pbase + k * NT + tid) * NSLICE + slice] = mm;
    }

    // ---- Group finalize (last of 16 slice-blocks in this group) ----
    __threadfence();
    if (tid == 0) {
        int c = atomicAdd(&g_cnt[group], 1);
        flag = (c == NSLICE - 1);
        if (flag) g_cnt[group] = 0;  // self-reset for graph replay
    }
    __syncthreads();
    if (!flag) return;
    __threadfence();  // acquire: other slice-blocks' g_part writes

    float s = 0.0f;
#pragma unroll
    for (int k = 0; k < KA; ++k) {
        const float* row = &g_part[(size_t)(pbase + k * NT + tid) * NSLICE];
        float mm = 3.4e38f;
#pragma unroll
        for (int q = 0; q < NSLICE / 4; ++q) {
            float4 v = *(const float4*)(row + q * 4);
            mm = fminf(mm, fminf(fminf(v.x, v.y), fminf(v.z, v.w)));
        }
        s += sqrtf(mm);
    }
    red[tid] = s;
    __syncthreads();
#pragma unroll
    for (int off = NT / 2; off > 0; off >>= 1) {
        if (tid < off) red[tid] += red[tid + off];
        __syncthreads();
    }

    // ---- Global finalize (last of 64 groups) ----
    if (tid == 0) {
        g_gsum[group] = red[0];
        __threadfence();
        int c = atomicAdd(&g_done, 1);
        if (c == NGROUP - 1) {
            g_done = 0;  // self-reset
            __threadfence();
            float total = 0.0f;
            for (int g = 0; g < NGROUP; ++g) total += g_gsum[g];
            out[0] = total * (1.0f / (float)NSLOT);
        }
    }
}

extern "C" void kernel_launch(void* const* d_in, const int* in_sizes, int n_in,
                              void* d_out, int out_size) {
    const float* pc1 = (const float*)d_in[0];
    const float* pc2 = (const float*)d_in[1];
    chamfer_fused<<<dim3(8, 4, 32), NT>>>(pc1, pc2, (float*)d_out);
}

// round 17
// speedup vs baseline: 1.3118x; 1.0010x over previous
#include <cuda_runtime.h>
#include <cstdint>

// Chamfer distance, B=4, N=4096, D=3, single fused kernel, 1024 x 64thr.
//
// min_j ||a-b_j||^2 = |a|^2 + min_j (|b_j|^2 - 2 a.b_j)
// KA=8 a-points/thread; inner step is ONE asm block:
//   3x fma.rn.f32x2 -> mov.b64 {lo,hi} -> 2x min.f32
// (producer, unpack and consumers adjacent so ptxas can coalesce the movs
// onto t's register pair — round-13 ncu showed ~4.2M un-coalesced MOV
// slots from the split-block version).
// j-loop runs in batches of 4 (8 LDS.128 then 32 steps), outer loop NOT
// unrolled: no prefetch index math, body ~3KB fits L0 I$.
//
// Grid: (8 a-chunks x 512, 4 batches, 32 = dir*16 + slice), 64 threads.
// Per-slice partial mins -> g_part[point][16] (no atomics, no init).
// Hierarchical tail: per-group (dir,batch,achunk = 64 groups of 16
// slice-blocks) last-finisher reduces its 512 points, globally-last group
// sums 64 partials in fixed order. Counters self-reset (graph-replay
// safe); fixed-order reductions -> deterministic.

#define NB 4
#define NP 4096
#define NSLOT (2 * NB * NP) /* 32768 */
#define NSLICE 16
#define NGROUP 64
#define KA 8
#define NT 64
#define APB (NT * KA) /* 512 a-points per block */

__device__ float g_part[NSLOT * NSLICE];  // [point][slice], 2MB
__device__ float g_gsum[NGROUP];
__device__ int g_cnt[NGROUP];  // zero-init; self-resetting
__device__ int g_done;         // zero-init; self-resetting

__device__ __forceinline__ unsigned long long pack2(float lo, float hi) {
    unsigned long long r;
    asm("mov.b64 %0, {%1, %2};" : "=l"(r) : "f"(lo), "f"(hi));
    return r;
}

// mlo = min(mlo, lo(t)); mhi = min(mhi, hi(t));
// t = v2.y + naz*v2.x + nay*v1.y + nax*v1.x   (packed f32x2)
__device__ __forceinline__ void step(float& mlo, float& mhi, unsigned long long nax,
                                     unsigned long long nay, unsigned long long naz,
                                     const ulonglong2 v1, const ulonglong2 v2) {
    asm("{\n\t"
        ".reg .b64 t;\n\t"
        ".reg .f32 lo, hi;\n\t"
        "fma.rn.f32x2 t, %2, %3, %4;\n\t"
        "fma.rn.f32x2 t, %5, %6, t;\n\t"
        "fma.rn.f32x2 t, %7, %8, t;\n\t"
        "mov.b64 {lo, hi}, t;\n\t"
        "min.f32 %0, %0, lo;\n\t"
        "min.f32 %1, %1, hi;\n\t"
        "}"
        : "+f"(mlo), "+f"(mhi)
        : "l"(naz), "l"(v2.x), "l"(v2.y), "l"(nay), "l"(v1.y), "l"(nax), "l"(v1.x));
}

__global__ __launch_bounds__(NT, 8) void chamfer_fused(const float* __restrict__ pc1,
                                                       const float* __restrict__ pc2,
                                                       float* __restrict__ out) {
    // 256 b-points as 128 packed pairs:
    // s1[j] = (bx0,bx1,by0,by1), s2[j] = (bz0,bz1,bw0,bw1), w = |b|^2
    __shared__ ulonglong2 s1[128];
    __shared__ ulonglong2 s2[128];
    __shared__ float red[NT];
    __shared__ int flag;

    const int tid = threadIdx.x;
    const int achunk = blockIdx.x;      // 0..7  (512 a-points)
    const int batch = blockIdx.y;       // 0..3
    const int dir = blockIdx.z >> 4;    // 0: pc1->pc2, 1: pc2->pc1
    const int slice = blockIdx.z & 15;  // 0..15 (256 b-points)
    const int group = dir * 32 + batch * 8 + achunk;

    const float* Abase = (dir ? pc2 : pc1) + (size_t)batch * NP * 3;
    const float* Bbase = (dir ? pc1 : pc2) + (size_t)batch * NP * 3 + (size_t)slice * 256 * 3;

    // Fill shared b-slice (4 points per thread).
#pragma unroll
    for (int r = 0; r < 4; ++r) {
        int jp = r * NT + tid;
        float bx = Bbase[jp * 3 + 0];
        float by = Bbase[jp * 3 + 1];
        float bz = Bbase[jp * 3 + 2];
        float bw = bx * bx + by * by + bz * bz;
        int pair = jp >> 1, half = jp & 1;
        float* p1 = (float*)&s1[pair];
        float* p2 = (float*)&s2[pair];
        p1[half] = bx;
        p1[2 + half] = by;
        p2[half] = bz;
        p2[2 + half] = bw;
    }
    __syncthreads();

    // Each thread owns KA=8 a-points.
    unsigned long long nax[KA], nay[KA], naz[KA];
    float asq[KA], mlo[KA], mhi[KA];
#pragma unroll
    for (int k = 0; k < KA; ++k) {
        int p = achunk * APB + k * NT + tid;
        float ax = Abase[p * 3 + 0];
        float ay = Abase[p * 3 + 1];
        float az = Abase[p * 3 + 2];
        nax[k] = pack2(-2.0f * ax, -2.0f * ax);
        nay[k] = pack2(-2.0f * ay, -2.0f * ay);
        naz[k] = pack2(-2.0f * az, -2.0f * az);
        asq[k] = ax * ax + ay * ay + az * az;
        mlo[k] = 3.4e38f;
        mhi[k] = 3.4e38f;
    }

    // Main loop: batches of 4 b-pairs (8 b-points), outer loop rolled.
#pragma unroll 1
    for (int jo = 0; jo < 128; jo += 4) {
        ulonglong2 v1a = s1[jo + 0], v2a = s2[jo + 0];
        ulonglong2 v1b = s1[jo + 1], v2b = s2[jo + 1];
        ulonglong2 v1c = s1[jo + 2], v2c = s2[jo + 2];
        ulonglong2 v1d = s1[jo + 3], v2d = s2[jo + 3];
#pragma unroll
        for (int k = 0; k < KA; ++k)
            step(mlo[k], mhi[k], nax[k], nay[k], naz[k], v1a, v2a);
#pragma unroll
        for (int k = 0; k < KA; ++k)
            step(mlo[k], mhi[k], nax[k], nay[k], naz[k], v1b, v2b);
#pragma unroll
        for (int k = 0; k < KA; ++k)
            step(mlo[k], mhi[k], nax[k], nay[k], naz[k], v1c, v2c);
#pragma unroll
        for (int k = 0; k < KA; ++k)
            step(mlo[k], mhi[k], nax[k], nay[k], naz[k], v1d, v2d);
    }

    // Partial mins (|a|^2 folded in, clamped at 0) -> g_part[point][slice].
    const int pbase = dir * (NB * NP) + batch * NP + achunk * APB;
#pragma unroll
    for (int k = 0; k < KA; ++k) {
        float mm = fmaxf(asq[k] + fminf(mlo[k], mhi[k]), 0.0f);
        g_part[(size_t)(pbase + k * NT + tid) * NSLICE + slice] = mm;
    }

    // ---- Group finalize (last of 16 slice-blocks in this group) ----
    __threadfence();
    if (tid == 0) {
        int c = atomicAdd(&g_cnt[group], 1);
        flag = (c == NSLICE - 1);
        if (flag) g_cnt[group] = 0;  // self-reset for graph replay
    }
    __syncthreads();
    if (!flag) return;
    __threadfence();  // acquire: other slice-blocks' g_part writes

    float s = 0.0f;
#pragma unroll
    for (int k = 0; k < KA; ++k) {
        const float* row = &g_part[(size_t)(pbase + k * NT + tid) * NSLICE];
        float mm = 3.4e38f;
#pragma unroll
        for (int q = 0; q < NSLICE / 4; ++q) {
            float4 v = *(const float4*)(row + q * 4);
            mm = fminf(mm, fminf(fminf(v.x, v.y), fminf(v.z, v.w)));
        }
        s += sqrtf(mm);
    }
    red[tid] = s;
    __syncthreads();
#pragma unroll
    for (int off = NT / 2; off > 0; off >>= 1) {
        if (tid < off) red[tid] += red[tid + off];
        __syncthreads();
    }

    // ---- Global finalize (last of 64 groups) ----
    if (tid == 0) {
        g_gsum[group] = red[0];
        __threadfence();
        int c = atomicAdd(&g_done, 1);
        if (c == NGROUP - 1) {
            g_done = 0;  // self-reset
            __threadfence();
            float total = 0.0f;
            for (int g = 0; g < NGROUP; ++g) total += g_gsum[g];
            out[0] = total * (1.0f / (float)NSLOT);
        }
    }
}

extern "C" void kernel_launch(void* const* d_in, const int* in_sizes, int n_in,
                              void* d_out, int out_size) {
    const float* pc1 = (const float*)d_in[0];
    const float* pc2 = (const float*)d_in[1];
    chamfer_fused<<<dim3(8, 4, 32), NT>>>(pc1, pc2, (float*)d_out);
}